// round 3
// baseline (speedup 1.0000x reference)
#include <cuda_runtime.h>
#include <cuda_bf16.h>

#define N_NODES 200000
#define N_SUPER 20000
#define N_EDGES 640000
#define EMB 256

// ---------------- scratch (static device globals; no allocs) ----------------
__device__ __align__(16) float g_x1[(size_t)N_NODES * EMB];    // x after supernode add
__device__ __align__(16) float g_agg[(size_t)N_NODES * EMB];   // sum of x1[src] per dst
__device__ __align__(16) float g_proj[(size_t)N_SUPER * EMB];  // snx @ W1^T + b1
__device__ __align__(16) float g_W1t[EMB * EMB];               // W1t[k][n] = W1[n][k]
__device__ __align__(16) float g_W2t[EMB * EMB];
__device__ __align__(16) float g_deg[N_NODES];                 // in-degree (float, exact)
__device__ __align__(16) int   g_rowmap[N_NODES];              // node -> supernode slot or -1
__device__ int g_is64;                                          // 1 if index tensors are int64

// ---------------- helpers ----------------
__device__ __forceinline__ void red_add_f32x4(float4* addr, float4 v) {
    asm volatile("red.global.add.v4.f32 [%0], {%1, %2, %3, %4};"
                 :: "l"(addr), "f"(v.x), "f"(v.y), "f"(v.z), "f"(v.w) : "memory");
}

__device__ __forceinline__ int load_idx(const void* p, int i) {
    if (g_is64) return (int)((const long long*)p)[i];
    return ((const int*)p)[i];
}

// ---------------- dtype detection ----------------
// If the edge buffer holds int64 (values < 2^31), every odd int32 word is 0.
// Genuine random int32 indices in [0, 200000) make that essentially impossible.
__global__ void k_detect(const int* __restrict__ ei_words) {
    int all_zero = 1;
    for (int k = 0; k < 64; k++)
        if (ei_words[2 * k + 1] != 0) { all_zero = 0; break; }
    g_is64 = all_zero;
}

// ---------------- prep: transpose weights ----------------
__global__ void k_transpose(const float* __restrict__ W1, const float* __restrict__ W2) {
    int i = blockIdx.x * blockDim.x + threadIdx.x;     // 0 .. 65535
    if (i >= EMB * EMB) return;
    int k = i >> 8, n = i & 255;
    g_W1t[i] = W1[n * EMB + k];
    g_W2t[i] = W2[n * EMB + k];
}

// ---------------- zero agg (float4 stores) ----------------
__global__ void k_zero_agg() {
    int i = blockIdx.x * blockDim.x + threadIdx.x;     // over N_NODES*64 float4
    if (i < N_NODES * (EMB / 4))
        ((float4*)g_agg)[i] = make_float4(0.f, 0.f, 0.f, 0.f);
}

__global__ void k_node_init() {
    int i = blockIdx.x * blockDim.x + threadIdx.x;
    if (i < N_NODES) { g_deg[i] = 0.f; g_rowmap[i] = -1; }
}

__global__ void k_set_rowmap(const void* __restrict__ sidx) {
    int s = blockIdx.x * blockDim.x + threadIdx.x;
    if (s < N_SUPER) {
        int v = load_idx(sidx, s);
        if (v >= 0 && v < N_NODES) g_rowmap[v] = s;
    }
}

// ---------------- fp32 GEMM:  C[row] = A[row] @ Wt (+ bias*scale + addv) ----------------
// M x 256 x 256. BM=64 rows/block, 256 threads, thread tile 8m x 8n, BK=32.
__global__ void __launch_bounds__(256)
k_gemm(const float* __restrict__ A, const float* __restrict__ Wt,
       const float* __restrict__ bias, float* __restrict__ C, int M,
       const float* __restrict__ addv,   // optional: added elementwise (x1), or nullptr
       const float* __restrict__ degw)   // optional: per-row bias scale (deg), or nullptr
{
    __shared__ float As[32][65];    // [k][m], padded
    __shared__ float Ws[32][256];   // [k][n]

    const int tid = threadIdx.x;
    const int mg  = tid >> 5;       // 0..7  (warp id = m-group)
    const int ng  = tid & 31;       // 0..31 (n-group: 8 cols each)
    const int row0 = blockIdx.x * 64;

    float acc[8][8];
#pragma unroll
    for (int i = 0; i < 8; i++)
#pragma unroll
        for (int j = 0; j < 8; j++) acc[i][j] = 0.f;

    for (int k0 = 0; k0 < EMB; k0 += 32) {
        // A tile: 64 rows x 32 k = 512 float4; 2 per thread. Store transposed [k][m].
#pragma unroll
        for (int t = 0; t < 2; t++) {
            int f  = tid + t * 256;
            int m  = f >> 3;
            int kq = f & 7;
            int row = row0 + m;
            float4 v = make_float4(0.f, 0.f, 0.f, 0.f);
            if (row < M)
                v = *(const float4*)(A + (size_t)row * EMB + k0 + kq * 4);
            As[kq * 4 + 0][m] = v.x;
            As[kq * 4 + 1][m] = v.y;
            As[kq * 4 + 2][m] = v.z;
            As[kq * 4 + 3][m] = v.w;
        }
        // W tile: 32 k x 256 n = 2048 float4; 8 per thread, coalesced.
#pragma unroll
        for (int t = 0; t < 8; t++) {
            int f  = tid + t * 256;
            int k  = f >> 6;
            int n4 = f & 63;
            *(float4*)&Ws[k][n4 * 4] =
                *(const float4*)(Wt + (size_t)(k0 + k) * EMB + n4 * 4);
        }
        __syncthreads();

#pragma unroll 8
        for (int kk = 0; kk < 32; kk++) {
            float a[8];
#pragma unroll
            for (int i = 0; i < 8; i++) a[i] = As[kk][mg * 8 + i];
            float4 w0 = *(float4*)&Ws[kk][ng * 8];
            float4 w1 = *(float4*)&Ws[kk][ng * 8 + 4];
            float w[8] = {w0.x, w0.y, w0.z, w0.w, w1.x, w1.y, w1.z, w1.w};
#pragma unroll
            for (int i = 0; i < 8; i++)
#pragma unroll
                for (int j = 0; j < 8; j++)
                    acc[i][j] += a[i] * w[j];
        }
        __syncthreads();
    }

    // epilogue
    float bl[8];
#pragma unroll
    for (int j = 0; j < 8; j++) bl[j] = bias[ng * 8 + j];

#pragma unroll
    for (int i = 0; i < 8; i++) {
        int row = row0 + mg * 8 + i;
        if (row >= M) break;
        float bs = degw ? degw[row] : 1.0f;
        size_t base = (size_t)row * EMB + ng * 8;
        float v[8];
#pragma unroll
        for (int j = 0; j < 8; j++) v[j] = acc[i][j] + bl[j] * bs;
        if (addv) {
            float4 a0 = *(const float4*)(addv + base);
            float4 a1 = *(const float4*)(addv + base + 4);
            v[0] += a0.x; v[1] += a0.y; v[2] += a0.z; v[3] += a0.w;
            v[4] += a1.x; v[5] += a1.y; v[6] += a1.z; v[7] += a1.w;
        }
        *(float4*)(C + base)     = make_float4(v[0], v[1], v[2], v[3]);
        *(float4*)(C + base + 4) = make_float4(v[4], v[5], v[6], v[7]);
    }
}

// ---------------- build x1 = x (+ proj at supernode rows) ----------------
__global__ void k_build_x1(const float* __restrict__ x) {
    int i = blockIdx.x * blockDim.x + threadIdx.x;   // over N_NODES*64 float4
    if (i >= N_NODES * (EMB / 4)) return;
    int row = i >> 6;
    int r = g_rowmap[row];
    float4 v = ((const float4*)x)[i];
    if (r >= 0) {
        float4 p = ((const float4*)g_proj)[(size_t)r * (EMB / 4) + (i & 63)];
        v.x += p.x; v.y += p.y; v.z += p.z; v.w += p.w;
    }
    ((float4*)g_x1)[i] = v;
}

// ---------------- edge aggregation: agg[dst] += x1[src]; deg[dst] += 1 ----------------
__global__ void __launch_bounds__(256) k_agg(const void* __restrict__ ei) {
    int e = blockIdx.x * 8 + (threadIdx.x >> 5);
    if (e >= N_EDGES) return;
    int lane = threadIdx.x & 31;
    int dst = load_idx(ei, e);              // row 0 = dst
    int src = load_idx(ei, N_EDGES + e);    // row 1 = src
    if (dst < 0 || dst >= N_NODES || src < 0 || src >= N_NODES) return;
    if (lane == 0) atomicAdd(&g_deg[dst], 1.0f);
    const float4* srow = (const float4*)(g_x1 + (size_t)src * EMB);
    float4*       drow = (float4*)(g_agg + (size_t)dst * EMB);
#pragma unroll
    for (int j = 0; j < 2; j++) {
        float4 v = srow[lane + 32 * j];
        red_add_f32x4(&drow[lane + 32 * j], v);
    }
}

// ---------------- launch ----------------
extern "C" void kernel_launch(void* const* d_in, const int* in_sizes, int n_in,
                              void* d_out, int out_size) {
    // Resolve inputs by element count (robust to metadata ordering).
    const float *x = nullptr, *snx = nullptr;
    const float *W1 = nullptr, *b1 = nullptr, *W2 = nullptr, *b2 = nullptr;
    const void  *ei = nullptr, *sidx = nullptr;

    for (int i = 0; i < n_in; i++) {
        int s = in_sizes[i];
        if      (s == N_NODES * EMB)  x    = (const float*)d_in[i];  // 51,200,000
        else if (s == N_SUPER * EMB)  snx  = (const float*)d_in[i];  //  5,120,000
        else if (s == 2 * N_EDGES)    ei   = d_in[i];                //  1,280,000
        else if (s == N_SUPER)        sidx = d_in[i];                //     20,000
        else if (s == N_NODES)        { /* graph_batch, unused */ }
        else if (s == EMB * EMB) {                                   //     65,536
            if (!W1) W1 = (const float*)d_in[i];
            else     W2 = (const float*)d_in[i];
        }
        else if (s == EMB) {                                         //        256
            if (!b1) b1 = (const float*)d_in[i];
            else     b2 = (const float*)d_in[i];
        }
    }
    float* out = (float*)d_out;

    void *p_agg, *p_x1, *p_proj, *p_W1t, *p_W2t, *p_deg;
    cudaGetSymbolAddress(&p_agg,  g_agg);
    cudaGetSymbolAddress(&p_x1,   g_x1);
    cudaGetSymbolAddress(&p_proj, g_proj);
    cudaGetSymbolAddress(&p_W1t,  g_W1t);
    cudaGetSymbolAddress(&p_W2t,  g_W2t);
    cudaGetSymbolAddress(&p_deg,  g_deg);

    // dtype detection + prep
    k_detect<<<1, 1>>>((const int*)ei);
    k_transpose<<<(EMB * EMB + 255) / 256, 256>>>(W1, W2);
    k_zero_agg<<<(N_NODES * (EMB / 4) + 255) / 256, 256>>>();
    k_node_init<<<(N_NODES + 255) / 256, 256>>>();
    k_set_rowmap<<<(N_SUPER + 255) / 256, 256>>>(sidx);

    // step 1: proj = snx @ W1^T + b1
    k_gemm<<<(N_SUPER + 63) / 64, 256>>>(snx, (const float*)p_W1t, b1,
                                         (float*)p_proj, N_SUPER, nullptr, nullptr);

    // x1 = x (+ proj at supernode rows)
    k_build_x1<<<(N_NODES * (EMB / 4) + 255) / 256, 256>>>(x);

    // step 2a: agg[dst] += x1[src]; deg[dst]++
    k_agg<<<(N_EDGES + 7) / 8, 256>>>(ei);

    // step 2b: out = x1 + agg @ W2^T + deg * b2
    k_gemm<<<(N_NODES + 63) / 64, 256>>>((const float*)p_agg, (const float*)p_W2t, b2,
                                         out, N_NODES, (const float*)p_x1,
                                         (const float*)p_deg);
}

// round 4
// speedup vs baseline: 1.7762x; 1.7762x over previous
#include <cuda_runtime.h>

#define N_NODES 200000
#define N_SUPER 20000
#define N_EDGES 640000
#define EMB 256

// ---------------- scratch (static device globals; no allocs) ----------------
__device__ __align__(16) float g_agg[(size_t)N_NODES * EMB];   // sum of x1[src] per dst
__device__ __align__(16) float g_proj[(size_t)N_SUPER * EMB];  // snx @ W1^T + b1
__device__ __align__(16) float g_deg[N_NODES];                 // in-degree (float, exact)
__device__ __align__(16) int   g_rowmap[N_NODES];              // node -> supernode slot or -1
__device__ int g_is64;                                         // 1 if index tensors are int64

// ---------------- helpers ----------------
__device__ __forceinline__ void red_add_f32x4(float4* addr, float4 v) {
    asm volatile("red.global.add.v4.f32 [%0], {%1, %2, %3, %4};"
                 :: "l"(addr), "f"(v.x), "f"(v.y), "f"(v.z), "f"(v.w) : "memory");
}

__device__ __forceinline__ int load_idx(const void* p, int i) {
    if (g_is64) return (int)((const long long*)p)[i];
    return ((const int*)p)[i];
}

__device__ __forceinline__ unsigned f2tf(float f) {
    unsigned u;
    asm("cvt.rna.tf32.f32 %0, %1;" : "=r"(u) : "f"(f));
    return u;
}

__device__ __forceinline__ void mma_tf32(float* c, const unsigned* a, const unsigned* b) {
    asm volatile("mma.sync.aligned.m16n8k8.row.col.f32.tf32.tf32.f32 "
                 "{%0,%1,%2,%3}, {%4,%5,%6,%7}, {%8,%9}, {%0,%1,%2,%3};"
                 : "+f"(c[0]), "+f"(c[1]), "+f"(c[2]), "+f"(c[3])
                 : "r"(a[0]), "r"(a[1]), "r"(a[2]), "r"(a[3]), "r"(b[0]), "r"(b[1]));
}

// ---------------- dtype detection ----------------
// If the edge buffer holds int64 (values < 2^31), every odd int32 word is 0.
__global__ void k_detect(const int* __restrict__ ei_words) {
    int all_zero = 1;
    for (int k = 0; k < 64; k++)
        if (ei_words[2 * k + 1] != 0) { all_zero = 0; break; }
    g_is64 = all_zero;
}

// ---------------- init ----------------
__global__ void k_zero_agg() {
    int i = blockIdx.x * blockDim.x + threadIdx.x;   // over N_NODES*64 float4
    if (i < N_NODES * (EMB / 4))
        ((float4*)g_agg)[i] = make_float4(0.f, 0.f, 0.f, 0.f);
}

__global__ void k_node_init() {
    int i = blockIdx.x * blockDim.x + threadIdx.x;
    if (i < N_NODES) { g_deg[i] = 0.f; g_rowmap[i] = -1; }
}

__global__ void k_set_rowmap(const void* __restrict__ sidx) {
    int s = blockIdx.x * blockDim.x + threadIdx.x;
    if (s < N_SUPER) {
        int v = load_idx(sidx, s);
        if (v >= 0 && v < N_NODES) g_rowmap[v] = s;
    }
}

// ---------------- tf32 tensor-core GEMM:  C = A @ W^T (+ epilogue) ----------------
// C[m][n] = sum_k A[m][k] * W[n][k].  W native layout [n][k] == mma "col" B operand.
// Block tile 128(M) x 128(N), BK=32, 8 warps (4 M x 2 N), warp tile 32x64.
// mode 0: C = acc + bias
// mode 1: C = acc + bias*deg[row] + xadd[row] + (rowmap[row]>=0 ? proj[rowmap[row]] : 0)
#define BM 128
#define BN 128
#define BK 32
#define PAD 36   // 36-word row stride -> conflict-free quad-pattern LDS

__global__ void __launch_bounds__(256, 2)
k_gemm_tf32(const float* __restrict__ A, const float* __restrict__ W,
            const float* __restrict__ bias, float* __restrict__ C, int M,
            const float* __restrict__ xadd, int final_mode)
{
    __shared__ unsigned As[BM * PAD];   // [m][k]
    __shared__ unsigned Bs[BN * PAD];   // [n][k]

    const int tid  = threadIdx.x;
    const int warp = tid >> 5, lane = tid & 31;
    const int wm   = warp >> 1, wn = warp & 1;     // 4 x 2 warp grid
    const int gid  = lane >> 2, tg = lane & 3;
    const int row0 = blockIdx.x * BM;
    const int n0   = blockIdx.y * BN;

    float c[2][8][4];
#pragma unroll
    for (int mt = 0; mt < 2; mt++)
#pragma unroll
        for (int nt = 0; nt < 8; nt++)
#pragma unroll
            for (int q = 0; q < 4; q++) c[mt][nt][q] = 0.f;

    for (int k0 = 0; k0 < EMB; k0 += BK) {
        // A tile: 128 x 32 floats; 4 float4 per thread; zero-fill OOB rows.
#pragma unroll
        for (int t = 0; t < 4; t++) {
            int f = tid + t * 256;
            int m = f >> 3, kq = f & 7;
            int row = row0 + m;
            float4 v = make_float4(0.f, 0.f, 0.f, 0.f);
            if (row < M) v = *(const float4*)(A + (size_t)row * EMB + k0 + kq * 4);
            unsigned* p = &As[m * PAD + kq * 4];
            p[0] = f2tf(v.x); p[1] = f2tf(v.y); p[2] = f2tf(v.z); p[3] = f2tf(v.w);
        }
        // B tile: W rows n0..n0+127, k0..k0+31.
#pragma unroll
        for (int t = 0; t < 4; t++) {
            int f = tid + t * 256;
            int n = f >> 3, kq = f & 7;
            float4 v = *(const float4*)(W + (size_t)(n0 + n) * EMB + k0 + kq * 4);
            unsigned* p = &Bs[n * PAD + kq * 4];
            p[0] = f2tf(v.x); p[1] = f2tf(v.y); p[2] = f2tf(v.z); p[3] = f2tf(v.w);
        }
        __syncthreads();

#pragma unroll
        for (int ks = 0; ks < BK; ks += 8) {
            unsigned a[2][4], b[8][2];
#pragma unroll
            for (int mt = 0; mt < 2; mt++) {
                int mb = wm * 32 + mt * 16 + gid;
                a[mt][0] = As[mb * PAD + ks + tg];
                a[mt][1] = As[(mb + 8) * PAD + ks + tg];
                a[mt][2] = As[mb * PAD + ks + tg + 4];
                a[mt][3] = As[(mb + 8) * PAD + ks + tg + 4];
            }
#pragma unroll
            for (int nt = 0; nt < 8; nt++) {
                int nb = wn * 64 + nt * 8 + gid;
                b[nt][0] = Bs[nb * PAD + ks + tg];
                b[nt][1] = Bs[nb * PAD + ks + tg + 4];
            }
#pragma unroll
            for (int mt = 0; mt < 2; mt++)
#pragma unroll
                for (int nt = 0; nt < 8; nt++)
                    mma_tf32(c[mt][nt], a[mt], b[nt]);
        }
        __syncthreads();
    }

    // ---------------- epilogue ----------------
#pragma unroll
    for (int mt = 0; mt < 2; mt++) {
#pragma unroll
        for (int half = 0; half < 2; half++) {      // c[0],c[1] vs c[2],c[3]
            int row = row0 + wm * 32 + mt * 16 + gid + half * 8;
            if (row >= M) continue;
            float dg = 0.f;
            int   r  = -1;
            const float* prow = nullptr;
            if (final_mode) {
                dg = g_deg[row];
                r  = g_rowmap[row];
                if (r >= 0) prow = g_proj + (size_t)r * EMB;
            }
#pragma unroll
            for (int nt = 0; nt < 8; nt++) {
                int col = n0 + wn * 64 + nt * 8 + 2 * tg;
                float v0 = c[mt][nt][half * 2 + 0];
                float v1 = c[mt][nt][half * 2 + 1];
                if (final_mode) {
                    v0 += bias[col]     * dg;
                    v1 += bias[col + 1] * dg;
                    float2 xv = *(const float2*)(xadd + (size_t)row * EMB + col);
                    v0 += xv.x; v1 += xv.y;
                    if (r >= 0) {
                        float2 pv = *(const float2*)(prow + col);
                        v0 += pv.x; v1 += pv.y;
                    }
                } else {
                    v0 += bias[col];
                    v1 += bias[col + 1];
                }
                *(float2*)(C + (size_t)row * EMB + col) = make_float2(v0, v1);
            }
        }
    }
}

// ---------------- edge aggregation: agg[dst] += x1[src]; deg[dst] += 1 ----------------
// x1[src] materialized on the fly: x[src] (+ proj[rowmap[src]] if supernode).
__global__ void __launch_bounds__(256) k_agg(const void* __restrict__ ei,
                                             const float* __restrict__ x) {
    int e = blockIdx.x * 8 + (threadIdx.x >> 5);
    if (e >= N_EDGES) return;
    int lane = threadIdx.x & 31;
    int dst = load_idx(ei, e);              // row 0 = dst
    int src = load_idx(ei, N_EDGES + e);    // row 1 = src
    if (dst < 0 || dst >= N_NODES || src < 0 || src >= N_NODES) return;
    if (lane == 0) atomicAdd(&g_deg[dst], 1.0f);
    int r = g_rowmap[src];
    const float4* srow = (const float4*)(x + (size_t)src * EMB);
    float4*       drow = (float4*)(g_agg + (size_t)dst * EMB);
    if (r >= 0) {
        const float4* prow = (const float4*)(g_proj + (size_t)r * EMB);
#pragma unroll
        for (int j = 0; j < 2; j++) {
            int i = lane + 32 * j;
            float4 v = srow[i], p = prow[i];
            v.x += p.x; v.y += p.y; v.z += p.z; v.w += p.w;
            red_add_f32x4(&drow[i], v);
        }
    } else {
#pragma unroll
        for (int j = 0; j < 2; j++) {
            int i = lane + 32 * j;
            red_add_f32x4(&drow[i], srow[i]);
        }
    }
}

// ---------------- launch ----------------
extern "C" void kernel_launch(void* const* d_in, const int* in_sizes, int n_in,
                              void* d_out, int out_size) {
    // Resolve inputs by element count (robust to metadata ordering).
    const float *x = nullptr, *snx = nullptr;
    const float *W1 = nullptr, *b1 = nullptr, *W2 = nullptr, *b2 = nullptr;
    const void  *ei = nullptr, *sidx = nullptr;

    for (int i = 0; i < n_in; i++) {
        int s = in_sizes[i];
        if      (s == N_NODES * EMB)  x    = (const float*)d_in[i];  // 51,200,000
        else if (s == N_SUPER * EMB)  snx  = (const float*)d_in[i];  //  5,120,000
        else if (s == 2 * N_EDGES)    ei   = d_in[i];                //  1,280,000
        else if (s == N_SUPER)        sidx = d_in[i];                //     20,000
        else if (s == N_NODES)        { /* graph_batch, unused */ }
        else if (s == EMB * EMB) {                                   //     65,536
            if (!W1) W1 = (const float*)d_in[i];
            else     W2 = (const float*)d_in[i];
        }
        else if (s == EMB) {                                         //        256
            if (!b1) b1 = (const float*)d_in[i];
            else     b2 = (const float*)d_in[i];
        }
    }
    float* out = (float*)d_out;

    void *p_agg, *p_proj;
    cudaGetSymbolAddress(&p_agg,  g_agg);
    cudaGetSymbolAddress(&p_proj, g_proj);

    // detection + init
    k_detect<<<1, 1>>>((const int*)ei);
    k_node_init<<<(N_NODES + 255) / 256, 256>>>();
    k_set_rowmap<<<(N_SUPER + 255) / 256, 256>>>(sidx);
    k_zero_agg<<<(N_NODES * (EMB / 4) + 255) / 256, 256>>>();

    // step 1: proj = snx @ W1^T + b1   (tf32 tensor cores)
    {
        dim3 grid((N_SUPER + BM - 1) / BM, EMB / BN);
        k_gemm_tf32<<<grid, 256>>>(snx, W1, b1, (float*)p_proj, N_SUPER, nullptr, 0);
    }

    // step 2a: agg[dst] += x1[src]; deg[dst]++   (x1 materialized on the fly)
    k_agg<<<(N_EDGES + 7) / 8, 256>>>(ei, x);

    // step 2b: out = x1 + agg @ W2^T + deg * b2  (tf32 tensor cores, fused epilogue)
    {
        dim3 grid((N_NODES + BM - 1) / BM, EMB / BN);
        k_gemm_tf32<<<grid, 256>>>((const float*)p_agg, W2, b2, out, N_NODES, x, 1);
    }
}

// round 5
// speedup vs baseline: 2.1026x; 1.1838x over previous
#include <cuda_runtime.h>

#define N_NODES 200000
#define N_SUPER 20000
#define N_EDGES 640000
#define EMB 256
#define NBLK 196   // ceil(N_NODES / 1024) scan blocks

// ---------------- scratch (static device globals; no allocs) ----------------
__device__ __align__(16) float g_agg[(size_t)N_NODES * EMB];   // sum of x1[src] per dst
__device__ __align__(16) float g_proj[(size_t)N_SUPER * EMB];  // snx @ W1^T + b1
__device__ __align__(16) int   g_rowmap[N_NODES];              // node -> supernode slot or -1
__device__ __align__(16) int   g_cnt[N_NODES];                 // histogram, then scatter cursor
__device__ __align__(16) int   g_off[N_NODES + 1];             // CSR offsets (exclusive scan)
__device__ __align__(16) int   g_esrc[N_EDGES];                // src ids sorted by dst
__device__ int g_bsum[NBLK];                                   // scan block sums
__device__ int g_bpre[NBLK];                                   // scanned block sums
__device__ int g_is64;                                         // 1 if index tensors are int64

// ---------------- helpers ----------------
__device__ __forceinline__ int load_idx(const void* p, int i) {
    if (g_is64) return (int)((const long long*)p)[i];
    return ((const int*)p)[i];
}

__device__ __forceinline__ unsigned f2tf(float f) {
    unsigned u;
    asm("cvt.rna.tf32.f32 %0, %1;" : "=r"(u) : "f"(f));
    return u;
}

__device__ __forceinline__ void mma_tf32(float* c, const unsigned* a, const unsigned* b) {
    asm volatile("mma.sync.aligned.m16n8k8.row.col.f32.tf32.tf32.f32 "
                 "{%0,%1,%2,%3}, {%4,%5,%6,%7}, {%8,%9}, {%0,%1,%2,%3};"
                 : "+f"(c[0]), "+f"(c[1]), "+f"(c[2]), "+f"(c[3])
                 : "r"(a[0]), "r"(a[1]), "r"(a[2]), "r"(a[3]), "r"(b[0]), "r"(b[1]));
}

// ---------------- dtype detection ----------------
__global__ void k_detect(const int* __restrict__ ei_words) {
    int all_zero = 1;
    for (int k = 0; k < 64; k++)
        if (ei_words[2 * k + 1] != 0) { all_zero = 0; break; }
    g_is64 = all_zero;
}

// ---------------- init: rowmap = -1, cnt = 0 ----------------
__global__ void k_init() {
    int i = blockIdx.x * blockDim.x + threadIdx.x;
    if (i < N_NODES) { g_rowmap[i] = -1; g_cnt[i] = 0; }
}

__global__ void k_set_rowmap(const void* __restrict__ sidx) {
    int s = blockIdx.x * blockDim.x + threadIdx.x;
    if (s < N_SUPER) {
        int v = load_idx(sidx, s);
        if (v >= 0 && v < N_NODES) g_rowmap[v] = s;
    }
}

// ---------------- CSR build: histogram -> scan -> scatter ----------------
__global__ void k_hist(const void* __restrict__ ei) {
    int e = blockIdx.x * blockDim.x + threadIdx.x;
    if (e >= N_EDGES) return;
    int dst = load_idx(ei, e);
    if (dst >= 0 && dst < N_NODES) atomicAdd(&g_cnt[dst], 1);
}

// per-block exclusive scan of 1024 elements (256 threads x 4)
__global__ void k_scan1() {
    __shared__ int s[256];
    int b = blockIdx.x, t = threadIdx.x;
    int base = b * 1024 + t * 4;
    int v[4], sum = 0;
#pragma unroll
    for (int i = 0; i < 4; i++) {
        v[i] = (base + i < N_NODES) ? g_cnt[base + i] : 0;
        sum += v[i];
    }
    s[t] = sum;
    __syncthreads();
#pragma unroll
    for (int off = 1; off < 256; off <<= 1) {
        int add = (t >= off) ? s[t - off] : 0;
        __syncthreads();
        s[t] += add;
        __syncthreads();
    }
    int run = (t ? s[t - 1] : 0);
#pragma unroll
    for (int i = 0; i < 4; i++) {
        if (base + i < N_NODES) g_off[base + i] = run;
        run += v[i];
    }
    if (t == 255) g_bsum[b] = s[255];
}

// single-block scan of NBLK block sums; also writes g_off[N_NODES] = total
__global__ void k_scan2() {
    __shared__ int s[256];
    int t = threadIdx.x;
    s[t] = (t < NBLK) ? g_bsum[t] : 0;
    __syncthreads();
#pragma unroll
    for (int off = 1; off < 256; off <<= 1) {
        int add = (t >= off) ? s[t - off] : 0;
        __syncthreads();
        s[t] += add;
        __syncthreads();
    }
    if (t < NBLK) g_bpre[t] = (t ? s[t - 1] : 0);
    if (t == 0) g_off[N_NODES] = s[NBLK - 1];
}

// finalize offsets; reset cnt to 0 (reused as scatter cursor)
__global__ void k_scan3() {
    int i = blockIdx.x * blockDim.x + threadIdx.x;
    if (i < N_NODES) {
        g_off[i] += g_bpre[i >> 10];
        g_cnt[i] = 0;
    }
}

__global__ void k_scatter(const void* __restrict__ ei) {
    int e = blockIdx.x * blockDim.x + threadIdx.x;
    if (e >= N_EDGES) return;
    int dst = load_idx(ei, e);
    int src = load_idx(ei, N_EDGES + e);
    if (dst < 0 || dst >= N_NODES || src < 0 || src >= N_NODES) return;
    int pos = g_off[dst] + atomicAdd(&g_cnt[dst], 1);
    g_esrc[pos] = src;
}

// ---------------- accumulate: agg[d] = sum_{e: dst=d} x1[src_e] (plain stores) ------
__global__ void __launch_bounds__(256) k_accum(const float* __restrict__ x) {
    int d = blockIdx.x * 8 + (threadIdx.x >> 5);
    if (d >= N_NODES) return;
    int lane = threadIdx.x & 31;
    int beg = g_off[d];
    int end = g_off[d + 1];
    float4 a0 = make_float4(0.f, 0.f, 0.f, 0.f);
    float4 a1 = make_float4(0.f, 0.f, 0.f, 0.f);
    for (int j = beg; j < end; j++) {
        int src = g_esrc[j];
        const float4* sr = (const float4*)(x + (size_t)src * EMB);
        float4 v0 = sr[lane], v1 = sr[lane + 32];
        int r = g_rowmap[src];
        if (r >= 0) {
            const float4* pr = (const float4*)(g_proj + (size_t)r * EMB);
            float4 p0 = pr[lane], p1 = pr[lane + 32];
            v0.x += p0.x; v0.y += p0.y; v0.z += p0.z; v0.w += p0.w;
            v1.x += p1.x; v1.y += p1.y; v1.z += p1.z; v1.w += p1.w;
        }
        a0.x += v0.x; a0.y += v0.y; a0.z += v0.z; a0.w += v0.w;
        a1.x += v1.x; a1.y += v1.y; a1.z += v1.z; a1.w += v1.w;
    }
    float4* dr = (float4*)(g_agg + (size_t)d * EMB);
    dr[lane]      = a0;
    dr[lane + 32] = a1;
}

// ---------------- tf32 tensor-core GEMM:  C = A @ W^T (+ epilogue) ----------------
// mode 0: C = acc + bias
// mode 1: C = acc + bias*deg[row] + xadd[row] + (rowmap[row]>=0 ? proj[rowmap[row]] : 0)
#define BM 128
#define BN 128
#define BK 32
#define PAD 36

__global__ void __launch_bounds__(256, 2)
k_gemm_tf32(const float* __restrict__ A, const float* __restrict__ W,
            const float* __restrict__ bias, float* __restrict__ C, int M,
            const float* __restrict__ xadd, int final_mode)
{
    __shared__ unsigned As[BM * PAD];   // [m][k]
    __shared__ unsigned Bs[BN * PAD];   // [n][k]

    const int tid  = threadIdx.x;
    const int warp = tid >> 5, lane = tid & 31;
    const int wm   = warp >> 1, wn = warp & 1;     // 4 x 2 warp grid
    const int gid  = lane >> 2, tg = lane & 3;
    const int row0 = blockIdx.x * BM;
    const int n0   = blockIdx.y * BN;

    float c[2][8][4];
#pragma unroll
    for (int mt = 0; mt < 2; mt++)
#pragma unroll
        for (int nt = 0; nt < 8; nt++)
#pragma unroll
            for (int q = 0; q < 4; q++) c[mt][nt][q] = 0.f;

    for (int k0 = 0; k0 < EMB; k0 += BK) {
#pragma unroll
        for (int t = 0; t < 4; t++) {
            int f = tid + t * 256;
            int m = f >> 3, kq = f & 7;
            int row = row0 + m;
            float4 v = make_float4(0.f, 0.f, 0.f, 0.f);
            if (row < M) v = *(const float4*)(A + (size_t)row * EMB + k0 + kq * 4);
            unsigned* p = &As[m * PAD + kq * 4];
            p[0] = f2tf(v.x); p[1] = f2tf(v.y); p[2] = f2tf(v.z); p[3] = f2tf(v.w);
        }
#pragma unroll
        for (int t = 0; t < 4; t++) {
            int f = tid + t * 256;
            int n = f >> 3, kq = f & 7;
            float4 v = *(const float4*)(W + (size_t)(n0 + n) * EMB + k0 + kq * 4);
            unsigned* p = &Bs[n * PAD + kq * 4];
            p[0] = f2tf(v.x); p[1] = f2tf(v.y); p[2] = f2tf(v.z); p[3] = f2tf(v.w);
        }
        __syncthreads();

#pragma unroll
        for (int ks = 0; ks < BK; ks += 8) {
            unsigned a[2][4], b[8][2];
#pragma unroll
            for (int mt = 0; mt < 2; mt++) {
                int mb = wm * 32 + mt * 16 + gid;
                a[mt][0] = As[mb * PAD + ks + tg];
                a[mt][1] = As[(mb + 8) * PAD + ks + tg];
                a[mt][2] = As[mb * PAD + ks + tg + 4];
                a[mt][3] = As[(mb + 8) * PAD + ks + tg + 4];
            }
#pragma unroll
            for (int nt = 0; nt < 8; nt++) {
                int nb = wn * 64 + nt * 8 + gid;
                b[nt][0] = Bs[nb * PAD + ks + tg];
                b[nt][1] = Bs[nb * PAD + ks + tg + 4];
            }
#pragma unroll
            for (int mt = 0; mt < 2; mt++)
#pragma unroll
                for (int nt = 0; nt < 8; nt++)
                    mma_tf32(c[mt][nt], a[mt], b[nt]);
        }
        __syncthreads();
    }

    // ---------------- epilogue ----------------
#pragma unroll
    for (int mt = 0; mt < 2; mt++) {
#pragma unroll
        for (int half = 0; half < 2; half++) {
            int row = row0 + wm * 32 + mt * 16 + gid + half * 8;
            if (row >= M) continue;
            float dg = 0.f;
            int   r  = -1;
            const float* prow = nullptr;
            if (final_mode) {
                dg = (float)(g_off[row + 1] - g_off[row]);   // in-degree
                r  = g_rowmap[row];
                if (r >= 0) prow = g_proj + (size_t)r * EMB;
            }
#pragma unroll
            for (int nt = 0; nt < 8; nt++) {
                int col = n0 + wn * 64 + nt * 8 + 2 * tg;
                float v0 = c[mt][nt][half * 2 + 0];
                float v1 = c[mt][nt][half * 2 + 1];
                if (final_mode) {
                    v0 += bias[col]     * dg;
                    v1 += bias[col + 1] * dg;
                    float2 xv = *(const float2*)(xadd + (size_t)row * EMB + col);
                    v0 += xv.x; v1 += xv.y;
                    if (r >= 0) {
                        float2 pv = *(const float2*)(prow + col);
                        v0 += pv.x; v1 += pv.y;
                    }
                } else {
                    v0 += bias[col];
                    v1 += bias[col + 1];
                }
                *(float2*)(C + (size_t)row * EMB + col) = make_float2(v0, v1);
            }
        }
    }
}

// ---------------- launch ----------------
extern "C" void kernel_launch(void* const* d_in, const int* in_sizes, int n_in,
                              void* d_out, int out_size) {
    const float *x = nullptr, *snx = nullptr;
    const float *W1 = nullptr, *b1 = nullptr, *W2 = nullptr, *b2 = nullptr;
    const void  *ei = nullptr, *sidx = nullptr;

    for (int i = 0; i < n_in; i++) {
        int s = in_sizes[i];
        if      (s == N_NODES * EMB)  x    = (const float*)d_in[i];
        else if (s == N_SUPER * EMB)  snx  = (const float*)d_in[i];
        else if (s == 2 * N_EDGES)    ei   = d_in[i];
        else if (s == N_SUPER)        sidx = d_in[i];
        else if (s == N_NODES)        { /* graph_batch, unused */ }
        else if (s == EMB * EMB) { if (!W1) W1 = (const float*)d_in[i]; else W2 = (const float*)d_in[i]; }
        else if (s == EMB)       { if (!b1) b1 = (const float*)d_in[i]; else b2 = (const float*)d_in[i]; }
    }
    float* out = (float*)d_out;

    void *p_agg, *p_proj;
    cudaGetSymbolAddress(&p_agg,  g_agg);
    cudaGetSymbolAddress(&p_proj, g_proj);

    // detection + init + CSR build
    k_detect<<<1, 1>>>((const int*)ei);
    k_init<<<(N_NODES + 255) / 256, 256>>>();
    k_set_rowmap<<<(N_SUPER + 255) / 256, 256>>>(sidx);
    k_hist<<<(N_EDGES + 255) / 256, 256>>>(ei);
    k_scan1<<<NBLK, 256>>>();
    k_scan2<<<1, 256>>>();
    k_scan3<<<(N_NODES + 255) / 256, 256>>>();
    k_scatter<<<(N_EDGES + 255) / 256, 256>>>(ei);

    // step 1: proj = snx @ W1^T + b1
    {
        dim3 grid((N_SUPER + BM - 1) / BM, EMB / BN);
        k_gemm_tf32<<<grid, 256>>>(snx, W1, b1, (float*)p_proj, N_SUPER, nullptr, 0);
    }

    // step 2a: agg[d] = sum of x1[src] over CSR range (register accumulate, plain store)
    k_accum<<<(N_NODES + 7) / 8, 256>>>(x);

    // step 2b: out = x1 + agg @ W2^T + deg * b2
    {
        dim3 grid((N_NODES + BM - 1) / BM, EMB / BN);
        k_gemm_tf32<<<grid, 256>>>((const float*)p_agg, W2, b2, out, N_NODES, x, 1);
    }
}

// round 9
// speedup vs baseline: 2.4045x; 1.1436x over previous
#include <cuda_runtime.h>

#define N_NODES 200000
#define N_SUPER 20000
#define N_EDGES 640000
#define EMB 256
#define NBLK 196   // ceil(N_NODES / 1024) scan blocks

// ---------------- scratch (static device globals; no allocs) ----------------
__device__ __align__(16) float g_agg[(size_t)N_NODES * EMB];   // sum of x1[src] per dst
__device__ __align__(16) float g_proj[(size_t)N_SUPER * EMB];  // x1 rows of supernodes: x[sidx]+snx@W1^T+b1
__device__ __align__(16) int   g_rowmap[N_NODES];              // node -> supernode slot or -1
__device__ __align__(16) int   g_snode[N_SUPER];               // slot -> node id
__device__ __align__(16) int   g_cnt[N_NODES];                 // histogram, then scatter cursor
__device__ __align__(16) int   g_off[N_NODES + 1];             // CSR offsets (exclusive scan)
__device__ __align__(16) int   g_esrc[N_EDGES];                // encoded src: node id, or N_NODES+slot
__device__ int g_bsum[NBLK];
__device__ int g_bpre[NBLK];
__device__ int g_is64;

// ---------------- helpers ----------------
__device__ __forceinline__ int load_idx(const void* p, int i) {
    if (g_is64) return (int)((const long long*)p)[i];
    return ((const int*)p)[i];
}

__device__ __forceinline__ unsigned f2tf(float f) {
    unsigned u;
    asm("cvt.rna.tf32.f32 %0, %1;" : "=r"(u) : "f"(f));
    return u;
}

__device__ __forceinline__ void mma_tf32(float* c, const unsigned* a, const unsigned* b) {
    asm volatile("mma.sync.aligned.m16n8k8.row.col.f32.tf32.tf32.f32 "
                 "{%0,%1,%2,%3}, {%4,%5,%6,%7}, {%8,%9}, {%0,%1,%2,%3};"
                 : "+f"(c[0]), "+f"(c[1]), "+f"(c[2]), "+f"(c[3])
                 : "r"(a[0]), "r"(a[1]), "r"(a[2]), "r"(a[3]), "r"(b[0]), "r"(b[1]));
}

__device__ __forceinline__ const float4* row_ptr(int idx, const float* x) {
    return (idx < N_NODES) ? (const float4*)(x + (size_t)idx * EMB)
                           : (const float4*)(g_proj + (size_t)(idx - N_NODES) * EMB);
}

__device__ __forceinline__ void acc4(float4& a, const float4 v) {
    a.x += v.x; a.y += v.y; a.z += v.z; a.w += v.w;
}

// ---------------- dtype detection ----------------
__global__ void k_detect(const int* __restrict__ ei_words) {
    int all_zero = 1;
    for (int k = 0; k < 64; k++)
        if (ei_words[2 * k + 1] != 0) { all_zero = 0; break; }
    g_is64 = all_zero;
}

// ---------------- init ----------------
__global__ void k_init() {
    int i = blockIdx.x * blockDim.x + threadIdx.x;
    if (i < N_NODES) { g_rowmap[i] = -1; g_cnt[i] = 0; }
    if (i < N_SUPER) g_snode[i] = 0;
}

__global__ void k_set_rowmap(const void* __restrict__ sidx) {
    int s = blockIdx.x * blockDim.x + threadIdx.x;
    if (s < N_SUPER) {
        int v = load_idx(sidx, s);
        if (v >= 0 && v < N_NODES) { g_rowmap[v] = s; g_snode[s] = v; }
    }
}

// ---------------- CSR build: histogram -> scan -> scatter ----------------
__global__ void k_hist(const void* __restrict__ ei) {
    int e = blockIdx.x * blockDim.x + threadIdx.x;
    if (e >= N_EDGES) return;
    int dst = load_idx(ei, e);
    if (dst >= 0 && dst < N_NODES) atomicAdd(&g_cnt[dst], 1);
}

__global__ void k_scan1() {
    __shared__ int s[256];
    int b = blockIdx.x, t = threadIdx.x;
    int base = b * 1024 + t * 4;
    int v[4], sum = 0;
#pragma unroll
    for (int i = 0; i < 4; i++) {
        v[i] = (base + i < N_NODES) ? g_cnt[base + i] : 0;
        sum += v[i];
    }
    s[t] = sum;
    __syncthreads();
#pragma unroll
    for (int off = 1; off < 256; off <<= 1) {
        int add = (t >= off) ? s[t - off] : 0;
        __syncthreads();
        s[t] += add;
        __syncthreads();
    }
    int run = (t ? s[t - 1] : 0);
#pragma unroll
    for (int i = 0; i < 4; i++) {
        if (base + i < N_NODES) g_off[base + i] = run;
        run += v[i];
    }
    if (t == 255) g_bsum[b] = s[255];
}

__global__ void k_scan2() {
    __shared__ int s[256];
    int t = threadIdx.x;
    s[t] = (t < NBLK) ? g_bsum[t] : 0;
    __syncthreads();
#pragma unroll
    for (int off = 1; off < 256; off <<= 1) {
        int add = (t >= off) ? s[t - off] : 0;
        __syncthreads();
        s[t] += add;
        __syncthreads();
    }
    if (t < NBLK) g_bpre[t] = (t ? s[t - 1] : 0);
    if (t == 0) g_off[N_NODES] = s[NBLK - 1];
}

__global__ void k_scan3() {
    int i = blockIdx.x * blockDim.x + threadIdx.x;
    if (i < N_NODES) {
        g_off[i] += g_bpre[i >> 10];
        g_cnt[i] = 0;
    }
}

// scatter with supernode resolution baked in: store node id, or N_NODES+slot
__global__ void k_scatter(const void* __restrict__ ei) {
    int e = blockIdx.x * blockDim.x + threadIdx.x;
    if (e >= N_EDGES) return;
    int dst = load_idx(ei, e);
    int src = load_idx(ei, N_EDGES + e);
    if (dst < 0 || dst >= N_NODES || src < 0 || src >= N_NODES) return;
    int r = g_rowmap[src];
    int enc = (r >= 0) ? (N_NODES + r) : src;
    int pos = g_off[dst] + atomicAdd(&g_cnt[dst], 1);
    g_esrc[pos] = enc;
}

// ---------------- accumulate: agg[d] = sum of x1[src] rows (MLP-8 batched) ----------
__global__ void __launch_bounds__(256) k_accum(const float* __restrict__ x) {
    int d = blockIdx.x * 8 + (threadIdx.x >> 5);
    if (d >= N_NODES) return;
    int lane = threadIdx.x & 31;
    int j   = g_off[d];
    int end = g_off[d + 1];
    float4 a0 = make_float4(0.f, 0.f, 0.f, 0.f);
    float4 a1 = make_float4(0.f, 0.f, 0.f, 0.f);

    for (; j + 4 <= end; j += 4) {
        int i0 = g_esrc[j], i1 = g_esrc[j + 1], i2 = g_esrc[j + 2], i3 = g_esrc[j + 3];
        const float4* p0 = row_ptr(i0, x);
        const float4* p1 = row_ptr(i1, x);
        const float4* p2 = row_ptr(i2, x);
        const float4* p3 = row_ptr(i3, x);
        float4 v00 = p0[lane], v01 = p0[lane + 32];
        float4 v10 = p1[lane], v11 = p1[lane + 32];
        float4 v20 = p2[lane], v21 = p2[lane + 32];
        float4 v30 = p3[lane], v31 = p3[lane + 32];
        acc4(a0, v00); acc4(a1, v01);
        acc4(a0, v10); acc4(a1, v11);
        acc4(a0, v20); acc4(a1, v21);
        acc4(a0, v30); acc4(a1, v31);
    }
    for (; j < end; j++) {
        const float4* p = row_ptr(g_esrc[j], x);
        acc4(a0, p[lane]); acc4(a1, p[lane + 32]);
    }
    float4* dr = (float4*)(g_agg + (size_t)d * EMB);
    dr[lane]      = a0;
    dr[lane + 32] = a1;
}

// ---------------- tf32 tensor-core GEMM:  C = A @ W^T (+ epilogue) ----------------
// Block tile 64(M) x 256(N) — full N in one pass, A streamed exactly once.
// 8 warps as 2(M) x 4(N); warp tile 32 x 64.
// mode 0 (proj):  C = acc + bias + x[g_snode[row]]          (=> C holds x1 supernode rows)
// mode 1 (final): C = acc + bias*deg + (r>=0 ? projx[r] : x[row])
#define BM 64
#define BN 256
#define BK 32
#define PAD 36

__global__ void __launch_bounds__(256, 2)
k_gemm_tf32(const float* __restrict__ A, const float* __restrict__ W,
            const float* __restrict__ bias, float* __restrict__ C, int M,
            const float* __restrict__ x, int final_mode)
{
    __shared__ unsigned As[BM * PAD];   // [m][k]
    __shared__ unsigned Bs[BN * PAD];   // [n][k]

    const int tid  = threadIdx.x;
    const int warp = tid >> 5, lane = tid & 31;
    const int wm   = warp >> 2, wn = warp & 3;     // 2 x 4 warp grid
    const int gid  = lane >> 2, tg = lane & 3;
    const int row0 = blockIdx.x * BM;

    float c[2][8][4];
#pragma unroll
    for (int mt = 0; mt < 2; mt++)
#pragma unroll
        for (int nt = 0; nt < 8; nt++)
#pragma unroll
            for (int q = 0; q < 4; q++) c[mt][nt][q] = 0.f;

    for (int k0 = 0; k0 < EMB; k0 += BK) {
        // A tile: 64 x 32 = 512 float4; 2 per thread
#pragma unroll
        for (int t = 0; t < 2; t++) {
            int f = tid + t * 256;
            int m = f >> 3, kq = f & 7;
            int row = row0 + m;
            float4 v = make_float4(0.f, 0.f, 0.f, 0.f);
            if (row < M) v = *(const float4*)(A + (size_t)row * EMB + k0 + kq * 4);
            unsigned* p = &As[m * PAD + kq * 4];
            p[0] = f2tf(v.x); p[1] = f2tf(v.y); p[2] = f2tf(v.z); p[3] = f2tf(v.w);
        }
        // B tile: 256 x 32 = 2048 float4; 8 per thread
#pragma unroll
        for (int t = 0; t < 8; t++) {
            int f = tid + t * 256;
            int n = f >> 3, kq = f & 7;
            float4 v = *(const float4*)(W + (size_t)n * EMB + k0 + kq * 4);
            unsigned* p = &Bs[n * PAD + kq * 4];
            p[0] = f2tf(v.x); p[1] = f2tf(v.y); p[2] = f2tf(v.z); p[3] = f2tf(v.w);
        }
        __syncthreads();

#pragma unroll
        for (int ks = 0; ks < BK; ks += 8) {
            unsigned a[2][4], b[8][2];
#pragma unroll
            for (int mt = 0; mt < 2; mt++) {
                int mb = wm * 32 + mt * 16 + gid;
                a[mt][0] = As[mb * PAD + ks + tg];
                a[mt][1] = As[(mb + 8) * PAD + ks + tg];
                a[mt][2] = As[mb * PAD + ks + tg + 4];
                a[mt][3] = As[(mb + 8) * PAD + ks + tg + 4];
            }
#pragma unroll
            for (int nt = 0; nt < 8; nt++) {
                int nb = wn * 64 + nt * 8 + gid;
                b[nt][0] = Bs[nb * PAD + ks + tg];
                b[nt][1] = Bs[nb * PAD + ks + tg + 4];
            }
#pragma unroll
            for (int mt = 0; mt < 2; mt++)
#pragma unroll
                for (int nt = 0; nt < 8; nt++)
                    mma_tf32(c[mt][nt], a[mt], b[nt]);
        }
        __syncthreads();
    }

    // ---------------- epilogue ----------------
#pragma unroll
    for (int mt = 0; mt < 2; mt++) {
#pragma unroll
        for (int half = 0; half < 2; half++) {
            int row = row0 + wm * 32 + mt * 16 + gid + half * 8;
            if (row >= M) continue;
            float dg = 1.f;
            const float* addrow;
            if (final_mode) {
                dg = (float)(g_off[row + 1] - g_off[row]);   // in-degree
                int r = g_rowmap[row];
                addrow = (r >= 0) ? (g_proj + (size_t)r * EMB)
                                  : (x + (size_t)row * EMB);
            } else {
                addrow = x + (size_t)g_snode[row] * EMB;     // projx = proj + x[snode]
            }
#pragma unroll
            for (int nt = 0; nt < 8; nt++) {
                int col = wn * 64 + nt * 8 + 2 * tg;
                float v0 = c[mt][nt][half * 2 + 0] + bias[col]     * dg;
                float v1 = c[mt][nt][half * 2 + 1] + bias[col + 1] * dg;
                float2 av = *(const float2*)(addrow + col);
                v0 += av.x; v1 += av.y;
                *(float2*)(C + (size_t)row * EMB + col) = make_float2(v0, v1);
            }
        }
    }
}

// ---------------- launch ----------------
extern "C" void kernel_launch(void* const* d_in, const int* in_sizes, int n_in,
                              void* d_out, int out_size) {
    const float *x = nullptr, *snx = nullptr;
    const float *W1 = nullptr, *b1 = nullptr, *W2 = nullptr, *b2 = nullptr;
    const void  *ei = nullptr, *sidx = nullptr;

    for (int i = 0; i < n_in; i++) {
        int s = in_sizes[i];
        if      (s == N_NODES * EMB)  x    = (const float*)d_in[i];
        else if (s == N_SUPER * EMB)  snx  = (const float*)d_in[i];
        else if (s == 2 * N_EDGES)    ei   = d_in[i];
        else if (s == N_SUPER)        sidx = d_in[i];
        else if (s == N_NODES)        { /* graph_batch, unused */ }
        else if (s == EMB * EMB) { if (!W1) W1 = (const float*)d_in[i]; else W2 = (const float*)d_in[i]; }
        else if (s == EMB)       { if (!b1) b1 = (const float*)d_in[i]; else b2 = (const float*)d_in[i]; }
    }
    float* out = (float*)d_out;

    void *p_agg, *p_proj;
    cudaGetSymbolAddress(&p_agg,  g_agg);
    cudaGetSymbolAddress(&p_proj, g_proj);

    // detection + init + CSR build
    k_detect<<<1, 1>>>((const int*)ei);
    k_init<<<(N_NODES + 255) / 256, 256>>>();
    k_set_rowmap<<<(N_SUPER + 255) / 256, 256>>>(sidx);
    k_hist<<<(N_EDGES + 255) / 256, 256>>>(ei);
    k_scan1<<<NBLK, 256>>>();
    k_scan2<<<1, 256>>>();
    k_scan3<<<(N_NODES + 255) / 256, 256>>>();
    k_scatter<<<(N_EDGES + 255) / 256, 256>>>(ei);

    // step 1: projx = x[sidx] + snx @ W1^T + b1  (supernode x1 rows)
    k_gemm_tf32<<<(N_SUPER + BM - 1) / BM, 256>>>(snx, W1, b1, (float*)p_proj,
                                                  N_SUPER, x, 0);

    // step 2a: agg[d] = sum of x1[src] rows over CSR range
    k_accum<<<(N_NODES + 7) / 8, 256>>>(x);

    // step 2b: out = x1 + agg @ W2^T + deg * b2
    k_gemm_tf32<<<(N_NODES + BM - 1) / BM, 256>>>((const float*)p_agg, W2, b2, out,
                                                  N_NODES, x, 1);
}